// round 9
// baseline (speedup 1.0000x reference)
#include <cuda_runtime.h>
#include <cuda_pipeline.h>
#include <math.h>

// Dihedral angle over 4 carbon atoms (indices 0,4,7,11 of 14) for B molecules.
// x: [B, 42] float32, out: [B] float32.
//
// R9 (= R8 resubmit after infra failure): finer-grained persistent pipelines.
// TILE=64 rows / 64 threads, double-buffered cp.async -> 21.5KB smem/CTA ->
// 10 CTAs/SM. Ten independent memory pipelines per SM (vs 5) to fill the
// request gaps that capped R3-R7 at 83% DRAM.

constexpr int TILE           = 64;           // rows per tile (1 row / thread)
constexpr int THREADS        = 64;
constexpr int FLOATS_PER_ROW = 42;           // 14 atoms * 3
constexpr int TILE_FLOATS    = TILE * FLOATS_PER_ROW;    // 2688
constexpr int CTAS_PER_SM    = 10;

__global__ __launch_bounds__(THREADS, CTAS_PER_SM)
void dihedral_kernel(const float* __restrict__ x,
                     float* __restrict__ out,
                     int B, int nTiles)
{
    __shared__ float sbuf[2][TILE_FLOATS];   // 2 * 10752 B = 21504 B

    const int tid = threadIdx.x;

    auto issue_tile = [&](int tile, int buf) {
        if (tile < nTiles) {
            const int rows   = min(TILE, B - tile * TILE);
            const int total  = rows * FLOATS_PER_ROW;
            const int total4 = total >> 2;
            const int rem    = total - (total4 << 2);      // 0 or 2
            // base = tile*64*42*4 = tile*10752 bytes -> 16B aligned
            const float4* __restrict__ s4 =
                reinterpret_cast<const float4*>(x + (size_t)tile * TILE_FLOATS);
            float4* d4 = reinterpret_cast<float4*>(sbuf[buf]);
            #pragma unroll 6
            for (int i = tid; i < total4; i += THREADS)
                __pipeline_memcpy_async(&d4[i], &s4[i], 16);
            if (tid < rem) {
                int i = (total4 << 2) + tid;
                __pipeline_memcpy_async(&sbuf[buf][i],
                                        &x[(size_t)tile * TILE_FLOATS + i], 4);
            }
        }
        __pipeline_commit();   // uniform group counting (possibly empty)
    };

    int tile = blockIdx.x;
    int buf  = 0;

    issue_tile(tile, buf);                       // prologue

    for (; tile < nTiles; tile += gridDim.x) {
        issue_tile(tile + gridDim.x, buf ^ 1);   // prefetch next

        __pipeline_wait_prior(1);                // current tile landed
        __syncthreads();                         // visible to all threads

        const int rows = min(TILE, B - tile * TILE);
        if (tid < rows) {
            const float* row = sbuf[buf] + tid * FLOATS_PER_ROW;

            // Carbon atoms 0,4,7,11 -> float offsets 0,12,21,33
            float c0x = row[0],  c0y = row[1],  c0z = row[2];
            float c1x = row[12], c1y = row[13], c1z = row[14];
            float c2x = row[21], c2y = row[22], c2z = row[23];
            float c3x = row[33], c3y = row[34], c3z = row[35];

            float v0x = c1x - c0x, v0y = c1y - c0y, v0z = c1z - c0z;
            float v1x = c2x - c1x, v1y = c2y - c1y, v1z = c2z - c1z;
            float v2x = c3x - c2x, v2y = c3y - c2y, v2z = c3z - c2z;

            // na = cross(-v0, v1)
            float nax = -(v0y * v1z - v0z * v1y);
            float nay = -(v0z * v1x - v0x * v1z);
            float naz = -(v0x * v1y - v0y * v1x);

            // nb = cross(-v1, v2)
            float nbx = -(v1y * v2z - v1z * v2y);
            float nby = -(v1z * v2x - v1x * v2z);
            float nbz = -(v1x * v2y - v1y * v2x);

            float xx = nax * nbx + nay * nby + naz * nbz;

            // xp = cross(na, nb)
            float xpx = nay * nbz - naz * nby;
            float xpy = naz * nbx - nax * nbz;
            float xpz = nax * nby - nay * nbx;

            float inv_n1 = rsqrtf(v1x * v1x + v1y * v1y + v1z * v1z);
            float yy = (v1x * xpx + v1y * xpy + v1z * xpz) * inv_n1;

            out[tile * TILE + tid] = atan2f(yy, xx);
        }
        __syncthreads();   // all reads done before this buffer is refilled
        buf ^= 1;
    }
}

extern "C" void kernel_launch(void* const* d_in, const int* in_sizes, int n_in,
                              void* d_out, int out_size)
{
    // Identify x (the big input) vs mask_matrix (56 elements, constant).
    int xi = 0;
    for (int i = 1; i < n_in; i++)
        if (in_sizes[i] > in_sizes[xi]) xi = i;

    const float* x = (const float*)d_in[xi];
    float* out = (float*)d_out;
    const int B = in_sizes[xi] / FLOATS_PER_ROW;     // 2,000,000
    const int nTiles = (B + TILE - 1) / TILE;        // 31250

    const int grid = 148 * CTAS_PER_SM;              // 1480: one full wave
    dihedral_kernel<<<grid, THREADS>>>(x, out, B, nTiles);
}